// round 1
// baseline (speedup 1.0000x reference)
#include <cuda_runtime.h>
#include <cuda_bf16.h>
#include <math.h>

// Problem dims (fixed by the reference)
#define B_SZ 4096
#define T_SZ 80
#define E_SZ 100
#define U_SZ 1024

// GEMM tiling
#define BM 128
#define BN 128
#define BK 16
#define TM 8
#define TN 8
// 256 threads per CTA: 16 (tx over N) x 16 (ty over M)

// Hidden-state ping-pong scratch (allocation-free rule: __device__ globals)
__device__ float g_h0a[B_SZ * U_SZ];
__device__ float g_h0b[B_SZ * U_SZ];
__device__ float g_h1a[B_SZ * U_SZ];
__device__ float g_h1b[B_SZ * U_SZ];

// ---------------------------------------------------------------------------
// Inner product on the staged tiles: acc[8][8] += As^T fragment * Bs fragment
// ---------------------------------------------------------------------------
__device__ __forceinline__ void mma_tile(const float As[BK][BM],
                                         const float Bs[BK][BN],
                                         int ty, int tx,
                                         float acc[TM][TN]) {
#pragma unroll
    for (int kk = 0; kk < BK; ++kk) {
        float4 a0 = *(const float4*)&As[kk][ty * TM + 0];
        float4 a1 = *(const float4*)&As[kk][ty * TM + 4];
        float4 b0 = *(const float4*)&Bs[kk][tx * TN + 0];
        float4 b1 = *(const float4*)&Bs[kk][tx * TN + 4];
        float a[TM] = {a0.x, a0.y, a0.z, a0.w, a1.x, a1.y, a1.z, a1.w};
        float b[TN] = {b0.x, b0.y, b0.z, b0.w, b1.x, b1.y, b1.z, b1.w};
#pragma unroll
        for (int i = 0; i < TM; ++i)
#pragma unroll
            for (int j = 0; j < TN; ++j)
                acc[i][j] = fmaf(a[i], b[j], acc[i][j]);
    }
}

// Stage one standard A tile (row-major [M,K], K multiple of 16, full-valid)
__device__ __forceinline__ void load_a_std(const float* __restrict__ A, int lda,
                                           int m0, int k0, int tid,
                                           float As[BK][BM]) {
#pragma unroll
    for (int i = 0; i < 2; ++i) {
        int slot = tid + i * 256;          // 512 float4 slots
        int r  = slot >> 2;                // 4 float4 per row (BK=16)
        int c4 = (slot & 3) << 2;
        float4 v = *(const float4*)(A + (size_t)(m0 + r) * lda + k0 + c4);
        As[c4 + 0][r] = v.x;
        As[c4 + 1][r] = v.y;
        As[c4 + 2][r] = v.z;
        As[c4 + 3][r] = v.w;
    }
}

// Stage one standard B tile (row-major [K, U_SZ])
__device__ __forceinline__ void load_b_std(const float* __restrict__ Bp,
                                           int k0, int n0, int tid,
                                           float Bs[BK][BN]) {
#pragma unroll
    for (int i = 0; i < 2; ++i) {
        int slot = tid + i * 256;          // 16 rows x 32 float4
        int r  = slot >> 5;
        int c4 = (slot & 31) << 2;
        *(float4*)&Bs[r][c4] =
            *(const float4*)(Bp + (size_t)(k0 + r) * U_SZ + n0 + c4);
    }
}

// ---------------------------------------------------------------------------
// Layer 0 step: h0_next = tanh( emb[inputs[:,t]] @ Wx0 + h0_prev @ Wh0 + b0 )
// ---------------------------------------------------------------------------
__global__ void __launch_bounds__(256)
step0_kernel(const int* __restrict__ inputs, int t,
             const float* __restrict__ emb,
             const float* __restrict__ Wx0,
             const float* __restrict__ h0_prev,
             const float* __restrict__ Wh0,
             const float* __restrict__ b0,
             float* __restrict__ h0_next) {
    __shared__ float As[BK][BM];
    __shared__ float Bs[BK][BN];

    const int tid = threadIdx.x;
    const int tx = tid & 15;
    const int ty = tid >> 4;
    const int n0 = blockIdx.x * BN;
    const int m0 = blockIdx.y * BM;

    float acc[TM][TN];
#pragma unroll
    for (int i = 0; i < TM; ++i)
#pragma unroll
        for (int j = 0; j < TN; ++j) acc[i][j] = 0.0f;

    // ---- Segment 1: recurrent h0_prev @ Wh0, K = 1024 ----
    for (int k0 = 0; k0 < U_SZ; k0 += BK) {
        load_a_std(h0_prev, U_SZ, m0, k0, tid, As);
        load_b_std(Wh0, k0, n0, tid, Bs);
        __syncthreads();
        mma_tile(As, Bs, ty, tx, acc);
        __syncthreads();
    }

    // ---- Segment 2: embedding gather @ Wx0, K = 100 (padded to 112) ----
    for (int k0 = 0; k0 < 112; k0 += BK) {
#pragma unroll
        for (int i = 0; i < 2; ++i) {
            int slot = tid + i * 256;
            int r  = slot >> 2;
            int c4 = (slot & 3) << 2;
            int e  = k0 + c4;
            float4 v = make_float4(0.f, 0.f, 0.f, 0.f);
            if (e < E_SZ) {   // E_SZ=100 is a multiple of 4: float4 fully valid or fully OOB
                int vid = inputs[(size_t)(m0 + r) * T_SZ + t];
                v = *(const float4*)(emb + (size_t)vid * E_SZ + e);
            }
            As[c4 + 0][r] = v.x;
            As[c4 + 1][r] = v.y;
            As[c4 + 2][r] = v.z;
            As[c4 + 3][r] = v.w;
        }
#pragma unroll
        for (int i = 0; i < 2; ++i) {
            int slot = tid + i * 256;
            int r  = slot >> 5;
            int c4 = (slot & 31) << 2;
            int k  = k0 + r;
            float4 v = make_float4(0.f, 0.f, 0.f, 0.f);
            if (k < E_SZ)
                v = *(const float4*)(Wx0 + (size_t)k * U_SZ + n0 + c4);
            *(float4*)&Bs[r][c4] = v;
        }
        __syncthreads();
        mma_tile(As, Bs, ty, tx, acc);
        __syncthreads();
    }

    // ---- Epilogue: +bias, tanh ----
    const int n_base = n0 + tx * TN;
    const int m_base = m0 + ty * TM;
    float bias[TN];
#pragma unroll
    for (int j = 0; j < TN; ++j) bias[j] = b0[n_base + j];
#pragma unroll
    for (int i = 0; i < TM; ++i) {
        float4 r0, r1;
        r0.x = tanhf(acc[i][0] + bias[0]);
        r0.y = tanhf(acc[i][1] + bias[1]);
        r0.z = tanhf(acc[i][2] + bias[2]);
        r0.w = tanhf(acc[i][3] + bias[3]);
        r1.x = tanhf(acc[i][4] + bias[4]);
        r1.y = tanhf(acc[i][5] + bias[5]);
        r1.z = tanhf(acc[i][6] + bias[6]);
        r1.w = tanhf(acc[i][7] + bias[7]);
        *(float4*)&h0_next[(size_t)(m_base + i) * U_SZ + n_base + 0] = r0;
        *(float4*)&h0_next[(size_t)(m_base + i) * U_SZ + n_base + 4] = r1;
    }
}

// ---------------------------------------------------------------------------
// Layer 1 step: h1_next = tanh( h0 @ Wx1 + h1_prev @ Wh1 + b1 )
// ---------------------------------------------------------------------------
__global__ void __launch_bounds__(256)
step1_kernel(const float* __restrict__ h0,
             const float* __restrict__ Wx1,
             const float* __restrict__ h1_prev,
             const float* __restrict__ Wh1,
             const float* __restrict__ b1,
             float* __restrict__ h1_next) {
    __shared__ float As[BK][BM];
    __shared__ float Bs[BK][BN];

    const int tid = threadIdx.x;
    const int tx = tid & 15;
    const int ty = tid >> 4;
    const int n0 = blockIdx.x * BN;
    const int m0 = blockIdx.y * BM;

    float acc[TM][TN];
#pragma unroll
    for (int i = 0; i < TM; ++i)
#pragma unroll
        for (int j = 0; j < TN; ++j) acc[i][j] = 0.0f;

    // Segment 1: h0 @ Wx1
    for (int k0 = 0; k0 < U_SZ; k0 += BK) {
        load_a_std(h0, U_SZ, m0, k0, tid, As);
        load_b_std(Wx1, k0, n0, tid, Bs);
        __syncthreads();
        mma_tile(As, Bs, ty, tx, acc);
        __syncthreads();
    }
    // Segment 2: h1_prev @ Wh1
    for (int k0 = 0; k0 < U_SZ; k0 += BK) {
        load_a_std(h1_prev, U_SZ, m0, k0, tid, As);
        load_b_std(Wh1, k0, n0, tid, Bs);
        __syncthreads();
        mma_tile(As, Bs, ty, tx, acc);
        __syncthreads();
    }

    const int n_base = n0 + tx * TN;
    const int m_base = m0 + ty * TM;
    float bias[TN];
#pragma unroll
    for (int j = 0; j < TN; ++j) bias[j] = b1[n_base + j];
#pragma unroll
    for (int i = 0; i < TM; ++i) {
        float4 r0, r1;
        r0.x = tanhf(acc[i][0] + bias[0]);
        r0.y = tanhf(acc[i][1] + bias[1]);
        r0.z = tanhf(acc[i][2] + bias[2]);
        r0.w = tanhf(acc[i][3] + bias[3]);
        r1.x = tanhf(acc[i][4] + bias[4]);
        r1.y = tanhf(acc[i][5] + bias[5]);
        r1.z = tanhf(acc[i][6] + bias[6]);
        r1.w = tanhf(acc[i][7] + bias[7]);
        *(float4*)&h1_next[(size_t)(m_base + i) * U_SZ + n_base + 0] = r0;
        *(float4*)&h1_next[(size_t)(m_base + i) * U_SZ + n_base + 4] = r1;
    }
}

// ---------------------------------------------------------------------------
// Head: out[b] = sigmoid( h1[b,:] . Wfc + bfc )   (one warp per row)
// ---------------------------------------------------------------------------
__global__ void __launch_bounds__(256)
final_kernel(const float* __restrict__ h1,
             const float* __restrict__ Wfc,
             const float* __restrict__ bfc,
             float* __restrict__ out) {
    int warp = (blockIdx.x * blockDim.x + threadIdx.x) >> 5;
    int lane = threadIdx.x & 31;
    if (warp >= B_SZ) return;
    float s = 0.0f;
#pragma unroll
    for (int u = lane; u < U_SZ; u += 32)
        s = fmaf(h1[(size_t)warp * U_SZ + u], Wfc[u], s);
#pragma unroll
    for (int o = 16; o > 0; o >>= 1) s += __shfl_xor_sync(0xffffffffu, s, o);
    if (lane == 0) {
        float z = s + bfc[0];
        out[warp] = 1.0f / (1.0f + expf(-z));
    }
}

__global__ void zero2_kernel(float* __restrict__ a, float* __restrict__ b) {
    int i = blockIdx.x * blockDim.x + threadIdx.x;   // over float4 slots
    ((float4*)a)[i] = make_float4(0.f, 0.f, 0.f, 0.f);
    ((float4*)b)[i] = make_float4(0.f, 0.f, 0.f, 0.f);
}

// ---------------------------------------------------------------------------
extern "C" void kernel_launch(void* const* d_in, const int* in_sizes, int n_in,
                              void* d_out, int out_size) {
    const int*   inputs = (const int*)  d_in[0];   // [B, T] int32
    const float* emb    = (const float*)d_in[1];   // [V, E]
    const float* Wx0    = (const float*)d_in[2];   // [E, U]
    const float* Wh0    = (const float*)d_in[3];   // [U, U]
    const float* b0     = (const float*)d_in[4];   // [U]
    const float* Wx1    = (const float*)d_in[5];   // [U, U]
    const float* Wh1    = (const float*)d_in[6];   // [U, U]
    const float* b1     = (const float*)d_in[7];   // [U]
    const float* Wfc    = (const float*)d_in[8];   // [U, 1]
    const float* bfc    = (const float*)d_in[9];   // [1]
    float* out = (float*)d_out;                    // [B, 1]

    float *h0a, *h0b, *h1a, *h1b;
    cudaGetSymbolAddress((void**)&h0a, g_h0a);
    cudaGetSymbolAddress((void**)&h0b, g_h0b);
    cudaGetSymbolAddress((void**)&h1a, g_h1a);
    cudaGetSymbolAddress((void**)&h1b, g_h1b);

    // zero the t=0 states (B*U floats each = 1M float4 per buffer)
    zero2_kernel<<<(B_SZ * U_SZ / 4) / 256, 256>>>(h0a, h1a);

    dim3 grid(U_SZ / BN, B_SZ / BM);   // (8, 32) = 256 CTAs

    const float* h0p = h0a; float* h0n = h0b;
    const float* h1p = h1a; float* h1n = h1b;
    for (int t = 0; t < T_SZ; ++t) {
        step0_kernel<<<grid, 256>>>(inputs, t, emb, Wx0, h0p, Wh0, b0, h0n);
        step1_kernel<<<grid, 256>>>(h0n, Wx1, h1p, Wh1, b1, h1n);
        { const float* tmp = h0p; h0p = h0n; h0n = (float*)tmp; }
        { const float* tmp = h1p; h1p = h1n; h1n = (float*)tmp; }
    }

    final_kernel<<<B_SZ / 8, 256>>>(h1p, Wfc, bfc, out);
}

// round 3
// speedup vs baseline: 2.9189x; 2.9189x over previous
#include <cuda_runtime.h>
#include <cuda_bf16.h>
#include <math.h>
#include <stdint.h>

#define B_SZ 4096
#define T_SZ 80
#define E_SZ 100
#define U_SZ 1024
#define V_SZ 10000

// CTA tile
#define BM 128
#define BN 128
#define BK 64
// smem stage layout (each matrix: 128 rows x 128B, SW128 swizzled)
#define A_HI 0
#define A_LO 16384
#define B_HI 32768
#define B_LO 49152
#define STAGE 65536
#define SMEM_DYN (2 * STAGE + 1024)

// ---------------------------------------------------------------------------
// Scratch (__device__ globals; no allocation allowed)
// ---------------------------------------------------------------------------
__device__ __align__(16) __nv_bfloat16 g_wt[6][U_SZ * U_SZ];  // Wh0,Wx1,Wh1 (hi,lo), [n][k]
__device__ __align__(16) float g_xw0[V_SZ * U_SZ];            // emb@Wx0 + b0
__device__ __align__(16) __nv_bfloat16 g_h[8][B_SZ * U_SZ];   // h0 ping/pong hi/lo, h1 ...

// ---------------------------------------------------------------------------
// helpers
// ---------------------------------------------------------------------------
__device__ __forceinline__ uint32_t smem_u32(const void* p) {
    uint32_t a;
    asm("{ .reg .u64 t; cvta.to.shared.u64 t, %1; cvt.u32.u64 %0, t; }"
        : "=r"(a) : "l"(p));
    return a;
}
__device__ __forceinline__ uint32_t swz128(uint32_t off) {
    return off ^ ((off >> 3) & 0x70);
}
__device__ __forceinline__ void cpa16(uint32_t dst, const void* src) {
    asm volatile("cp.async.cg.shared.global [%0], [%1], 16;" :: "r"(dst), "l"(src));
}
__device__ __forceinline__ void ldsm4(uint32_t* r, uint32_t addr) {
    asm volatile("ldmatrix.sync.aligned.m8n8.x4.shared.b16 {%0,%1,%2,%3}, [%4];"
                 : "=r"(r[0]), "=r"(r[1]), "=r"(r[2]), "=r"(r[3]) : "r"(addr));
}
__device__ __forceinline__ void mma16816(float* c, const uint32_t* a, const uint32_t* b) {
    asm volatile(
        "mma.sync.aligned.m16n8k16.row.col.f32.bf16.bf16.f32 "
        "{%0,%1,%2,%3}, {%4,%5,%6,%7}, {%8,%9}, {%0,%1,%2,%3};"
        : "+f"(c[0]), "+f"(c[1]), "+f"(c[2]), "+f"(c[3])
        : "r"(a[0]), "r"(a[1]), "r"(a[2]), "r"(a[3]), "r"(b[0]), "r"(b[1]));
}

// ---------------------------------------------------------------------------
// Main step kernel: D[128x128] = sum over nseg segments of 3-term bf16 split
// GEMM (A[m][k] row-major x W[n][k]); epilogue tanh(D + xw0_gather|bias),
// write hi/lo bf16 state.
// ---------------------------------------------------------------------------
__global__ void __launch_bounds__(256, 1)
rnn_step_kernel(const __nv_bfloat16* __restrict__ A0hi, const __nv_bfloat16* __restrict__ A0lo,
                const __nv_bfloat16* __restrict__ W0hi, const __nv_bfloat16* __restrict__ W0lo,
                const __nv_bfloat16* __restrict__ A1hi, const __nv_bfloat16* __restrict__ A1lo,
                const __nv_bfloat16* __restrict__ W1hi, const __nv_bfloat16* __restrict__ W1lo,
                int nseg,
                const float* __restrict__ bias,   // layer-1 only (layer-0 folded in xw0)
                const float* __restrict__ xw0,    // non-null for layer 0
                const int* __restrict__ inputs, int t,
                __nv_bfloat16* __restrict__ outhi, __nv_bfloat16* __restrict__ outlo) {
    extern __shared__ char dsm[];
    const uint32_t tile = (smem_u32(dsm) + 1023u) & ~1023u;

    const int tid = threadIdx.x;
    const int wid = tid >> 5;
    const int lane = tid & 31;
    const int m0 = blockIdx.y * BM;
    const int n0 = blockIdx.x * BN;

    const int warp_m = wid & 1;        // 2 warps along M
    const int warp_n = wid >> 1;       // 4 warps along N
    const int mW = warp_m * 64;
    const int nW = warp_n * 32;

    const __nv_bfloat16* __restrict__ Ah[2] = {A0hi, A1hi};
    const __nv_bfloat16* __restrict__ Al[2] = {A0lo, A1lo};
    const __nv_bfloat16* __restrict__ Wh[2] = {W0hi, W1hi};
    const __nv_bfloat16* __restrict__ Wl[2] = {W0lo, W1lo};

    const int NST = nseg * (U_SZ / BK);    // 16 or 32 stages

    // precomputed per-thread load indices (4 chunks per matrix)
    int lrow[4], lcol[4];
    uint32_t ldst[4];
#pragma unroll
    for (int i = 0; i < 4; ++i) {
        int c = tid + i * 256;
        lrow[i] = c >> 3;
        lcol[i] = c & 7;
        ldst[i] = swz128((uint32_t)(lrow[i] * 128 + lcol[i] * 16));
    }

    auto load_stage = [&](int s, int buf) {
        const int seg = s >> 4;
        const int k0 = (s & 15) * BK;
        const uint32_t bb = tile + (uint32_t)buf * STAGE;
        const __nv_bfloat16* ah = Ah[seg];
        const __nv_bfloat16* al = Al[seg];
        const __nv_bfloat16* wh = Wh[seg];
        const __nv_bfloat16* wl = Wl[seg];
#pragma unroll
        for (int i = 0; i < 4; ++i) {
            size_t ga = (size_t)(m0 + lrow[i]) * U_SZ + k0 + lcol[i] * 8;
            size_t gb = (size_t)(n0 + lrow[i]) * U_SZ + k0 + lcol[i] * 8;
            cpa16(bb + A_HI + ldst[i], ah + ga);
            cpa16(bb + A_LO + ldst[i], al + ga);
            cpa16(bb + B_HI + ldst[i], wh + gb);
            cpa16(bb + B_LO + ldst[i], wl + gb);
        }
        asm volatile("cp.async.commit_group;" ::: "memory");
    };

    float acc[4][4][4];
#pragma unroll
    for (int i = 0; i < 4; ++i)
#pragma unroll
        for (int j = 0; j < 4; ++j)
#pragma unroll
            for (int q = 0; q < 4; ++q) acc[i][j][q] = 0.0f;

    // per-warp ldmatrix source offsets (within a matrix region, pre-swizzle inputs)
    const int a_row = mW + (lane & 15);         // + i*16
    const int a_cg  = (lane >> 4) * 16;         // 16B col group
    const int b_q   = lane >> 3;
    const int b_row = nW + ((b_q >> 1) * 8) + (lane & 7);   // + j2*16
    const int b_cg  = (b_q & 1) * 16;

    load_stage(0, 0);

    for (int s = 0; s < NST; ++s) {
        const int buf = s & 1;
        if (s + 1 < NST) {
            load_stage(s + 1, buf ^ 1);
            asm volatile("cp.async.wait_group 1;" ::: "memory");
        } else {
            asm volatile("cp.async.wait_group 0;" ::: "memory");
        }
        __syncthreads();

        const uint32_t bb = tile + (uint32_t)buf * STAGE;
#pragma unroll
        for (int ks = 0; ks < 4; ++ks) {
            uint32_t ah4[4][4], al4[4][4], bh4[4][2], bl4[4][2];
#pragma unroll
            for (int i = 0; i < 4; ++i) {
                uint32_t off = swz128((uint32_t)((a_row + i * 16) * 128 + ks * 32 + a_cg));
                ldsm4(ah4[i], bb + A_HI + off);
                ldsm4(al4[i], bb + A_LO + off);
            }
#pragma unroll
            for (int j2 = 0; j2 < 2; ++j2) {
                uint32_t off = swz128((uint32_t)((b_row + j2 * 16) * 128 + ks * 32 + b_cg));
                uint32_t r[4];
                ldsm4(r, bb + B_HI + off);
                bh4[j2 * 2][0] = r[0]; bh4[j2 * 2][1] = r[1];
                bh4[j2 * 2 + 1][0] = r[2]; bh4[j2 * 2 + 1][1] = r[3];
                ldsm4(r, bb + B_LO + off);
                bl4[j2 * 2][0] = r[0]; bl4[j2 * 2][1] = r[1];
                bl4[j2 * 2 + 1][0] = r[2]; bl4[j2 * 2 + 1][1] = r[3];
            }
#pragma unroll
            for (int i = 0; i < 4; ++i)
#pragma unroll
                for (int j = 0; j < 4; ++j)
                    mma16816(acc[i][j], ah4[i], bh4[j]);
#pragma unroll
            for (int i = 0; i < 4; ++i)
#pragma unroll
                for (int j = 0; j < 4; ++j)
                    mma16816(acc[i][j], ah4[i], bl4[j]);
#pragma unroll
            for (int i = 0; i < 4; ++i)
#pragma unroll
                for (int j = 0; j < 4; ++j)
                    mma16816(acc[i][j], al4[i], bh4[j]);
        }
        __syncthreads();
    }

    // ---- epilogue ----
    const int gp = lane >> 2;
    const int t4 = lane & 3;
#pragma unroll
    for (int i = 0; i < 4; ++i) {
#pragma unroll
        for (int rh = 0; rh < 2; ++rh) {
            const int m = m0 + mW + i * 16 + gp + rh * 8;
            const float* xr = nullptr;
            if (xw0) xr = xw0 + (size_t)inputs[(size_t)m * T_SZ + t] * U_SZ;
#pragma unroll
            for (int j = 0; j < 4; ++j) {
                const int col = n0 + nW + j * 8 + t4 * 2;
                float v0 = acc[i][j][rh * 2 + 0];
                float v1 = acc[i][j][rh * 2 + 1];
                if (xr) { v0 += xr[col]; v1 += xr[col + 1]; }
                else    { v0 += bias[col]; v1 += bias[col + 1]; }
                float h0f = tanhf(v0), h1f = tanhf(v1);
                __nv_bfloat16 h0 = __float2bfloat16(h0f);
                __nv_bfloat16 h1 = __float2bfloat16(h1f);
                __nv_bfloat16 l0 = __float2bfloat16(h0f - __bfloat162float(h0));
                __nv_bfloat16 l1 = __float2bfloat16(h1f - __bfloat162float(h1));
                uint32_t ph = (uint32_t)__bfloat16_as_ushort(h0) |
                              ((uint32_t)__bfloat16_as_ushort(h1) << 16);
                uint32_t pl = (uint32_t)__bfloat16_as_ushort(l0) |
                              ((uint32_t)__bfloat16_as_ushort(l1) << 16);
                *(uint32_t*)(outhi + (size_t)m * U_SZ + col) = ph;
                *(uint32_t*)(outlo + (size_t)m * U_SZ + col) = pl;
            }
        }
    }
}

// ---------------------------------------------------------------------------
// Prep: transpose + bf16-split the three recurrent weight matrices
// ---------------------------------------------------------------------------
__global__ void __launch_bounds__(256)
transpose_split_kernel(const float* __restrict__ W0, const float* __restrict__ W1,
                       const float* __restrict__ W2) {
    __shared__ float tilebuf[32][33];
    const int z = blockIdx.z;
    const float* W = (z == 0) ? W0 : ((z == 1) ? W1 : W2);
    __nv_bfloat16* Th = g_wt[2 * z];
    __nv_bfloat16* Tl = g_wt[2 * z + 1];
    const int tx = threadIdx.x & 31, ty = threadIdx.x >> 5;
    const int x = blockIdx.x * 32 + tx;
    const int y0 = blockIdx.y * 32;
#pragma unroll
    for (int j = 0; j < 32; j += 8)
        tilebuf[ty + j][tx] = W[(size_t)(y0 + ty + j) * U_SZ + x];
    __syncthreads();
    const int x2 = blockIdx.y * 32 + tx;
#pragma unroll
    for (int j = 0; j < 32; j += 8) {
        int n = blockIdx.x * 32 + ty + j;
        float v = tilebuf[tx][ty + j];
        __nv_bfloat16 h = __float2bfloat16(v);
        Th[(size_t)n * U_SZ + x2] = h;
        Tl[(size_t)n * U_SZ + x2] = __float2bfloat16(v - __bfloat162float(h));
    }
}

// ---------------------------------------------------------------------------
// Prep: xw0[v][n] = b0[n] + sum_k emb[v,k] * Wx0[k,n]
// ---------------------------------------------------------------------------
__global__ void __launch_bounds__(256)
xw0_kernel(const float* __restrict__ emb, const float* __restrict__ Wx0,
           const float* __restrict__ b0, float* __restrict__ xw0) {
    __shared__ float es[16][104];
    const int v0 = blockIdx.y * 16;
    const int n = blockIdx.x * 256 + threadIdx.x;
    for (int i = threadIdx.x; i < 16 * E_SZ; i += 256) {
        int r = i / E_SZ, c = i % E_SZ;
        es[r][c] = emb[(size_t)(v0 + r) * E_SZ + c];
    }
    __syncthreads();
    float acc[16];
    float bv = b0[n];
#pragma unroll
    for (int i = 0; i < 16; ++i) acc[i] = bv;
    for (int k = 0; k < E_SZ; ++k) {
        float w = Wx0[(size_t)k * U_SZ + n];
#pragma unroll
        for (int i = 0; i < 16; ++i) acc[i] = fmaf(es[i][k], w, acc[i]);
    }
#pragma unroll
    for (int i = 0; i < 16; ++i)
        xw0[(size_t)(v0 + i) * U_SZ + n] = acc[i];
}

// ---------------------------------------------------------------------------
__global__ void zero4_kernel(__nv_bfloat16* a, __nv_bfloat16* b,
                             __nv_bfloat16* c, __nv_bfloat16* d) {
    size_t i = (size_t)blockIdx.x * blockDim.x + threadIdx.x;
    uint4 z = make_uint4(0, 0, 0, 0);
    ((uint4*)a)[i] = z; ((uint4*)b)[i] = z;
    ((uint4*)c)[i] = z; ((uint4*)d)[i] = z;
}

// ---------------------------------------------------------------------------
__global__ void __launch_bounds__(256)
final_kernel(const __nv_bfloat16* __restrict__ h1hi, const __nv_bfloat16* __restrict__ h1lo,
             const float* __restrict__ Wfc, const float* __restrict__ bfc,
             float* __restrict__ out) {
    int warp = (blockIdx.x * blockDim.x + threadIdx.x) >> 5;
    int lane = threadIdx.x & 31;
    if (warp >= B_SZ) return;
    float s = 0.0f;
#pragma unroll
    for (int u = lane; u < U_SZ; u += 32) {
        float h = __bfloat162float(h1hi[(size_t)warp * U_SZ + u]) +
                  __bfloat162float(h1lo[(size_t)warp * U_SZ + u]);
        s = fmaf(h, Wfc[u], s);
    }
#pragma unroll
    for (int o = 16; o > 0; o >>= 1) s += __shfl_xor_sync(0xffffffffu, s, o);
    if (lane == 0) {
        float z = s + bfc[0];
        out[warp] = 1.0f / (1.0f + expf(-z));
    }
}

// ---------------------------------------------------------------------------
extern "C" void kernel_launch(void* const* d_in, const int* in_sizes, int n_in,
                              void* d_out, int out_size) {
    const int*   inputs = (const int*)  d_in[0];
    const float* emb    = (const float*)d_in[1];
    const float* Wx0    = (const float*)d_in[2];
    const float* Wh0    = (const float*)d_in[3];
    const float* b0     = (const float*)d_in[4];
    const float* Wx1    = (const float*)d_in[5];
    const float* Wh1    = (const float*)d_in[6];
    const float* b1     = (const float*)d_in[7];
    const float* Wfc    = (const float*)d_in[8];
    const float* bfc    = (const float*)d_in[9];
    float* out = (float*)d_out;

    cudaFuncSetAttribute(rnn_step_kernel,
                         cudaFuncAttributeMaxDynamicSharedMemorySize, SMEM_DYN);

    __nv_bfloat16 *wt, *h;
    float* xw0;
    cudaGetSymbolAddress((void**)&wt, g_wt);
    cudaGetSymbolAddress((void**)&xw0, g_xw0);
    cudaGetSymbolAddress((void**)&h, g_h);

    __nv_bfloat16* Wh0h = wt + 0ull * U_SZ * U_SZ;
    __nv_bfloat16* Wh0l = wt + 1ull * U_SZ * U_SZ;
    __nv_bfloat16* Wx1h = wt + 2ull * U_SZ * U_SZ;
    __nv_bfloat16* Wx1l = wt + 3ull * U_SZ * U_SZ;
    __nv_bfloat16* Wh1h = wt + 4ull * U_SZ * U_SZ;
    __nv_bfloat16* Wh1l = wt + 5ull * U_SZ * U_SZ;

    const size_t HS = (size_t)B_SZ * U_SZ;
    __nv_bfloat16* h0[2][2] = {{h + 0 * HS, h + 1 * HS}, {h + 2 * HS, h + 3 * HS}};
    __nv_bfloat16* h1[2][2] = {{h + 4 * HS, h + 5 * HS}, {h + 6 * HS, h + 7 * HS}};

    transpose_split_kernel<<<dim3(32, 32, 3), 256>>>(Wh0, Wx1, Wh1);
    xw0_kernel<<<dim3(4, V_SZ / 16), 256>>>(emb, Wx0, b0, xw0);
    zero4_kernel<<<(unsigned)(HS / 8 / 256), 256>>>(h0[0][0], h0[0][1], h1[0][0], h1[0][1]);

    dim3 grid(U_SZ / BN, B_SZ / BM);   // (8, 32) = 256 CTAs

    int p0 = 0, p1 = 0;
    for (int t = 0; t < T_SZ; ++t) {
        rnn_step_kernel<<<grid, 256, SMEM_DYN>>>(
            h0[p0][0], h0[p0][1], Wh0h, Wh0l,
            nullptr, nullptr, nullptr, nullptr, 1,
            nullptr, xw0, inputs, t,
            h0[p0 ^ 1][0], h0[p0 ^ 1][1]);
        p0 ^= 1;
        rnn_step_kernel<<<grid, 256, SMEM_DYN>>>(
            h0[p0][0], h0[p0][1], Wx1h, Wx1l,
            h1[p1][0], h1[p1][1], Wh1h, Wh1l, 2,
            b1, nullptr, nullptr, 0,
            h1[p1 ^ 1][0], h1[p1 ^ 1][1]);
        p1 ^= 1;
    }

    final_kernel<<<B_SZ / 8, 256>>>(h1[p1][0], h1[p1][1], Wfc, bfc, out);
}